// round 1
// baseline (speedup 1.0000x reference)
#include <cuda_runtime.h>
#include <math.h>

// Problem constants (fixed by setup_inputs)
#define G     8
#define HID   4000
#define Q     512
#define QG    64      // Q / G
#define LWIN  6       // L
#define INSZ  76      // QG + 2*L
#define STEPS 400
#define EPS   32
#define NHIST 64      // u_hist rows

// Double-buffered hidden state (scratch; device globals are the allowed scratch path)
__device__ float g_h[2][G * HID];

// ---------------------------------------------------------------------------
// One ESN step: h_out = 0.4*h_in + 0.6*tanh(W_in@ug + W_hh@h_in)
// grid = (CHUNKS, G), block = 256. Warp-per-row, float4 streaming of W_hh.
// ---------------------------------------------------------------------------
__global__ void __launch_bounds__(256) step_kernel(
    const float* __restrict__ W_in,   // [G, HID, INSZ]
    const float* __restrict__ W_hh,   // [G, HID, HID]
    const float* __restrict__ u,      // [Q] (current input vector)
    const float* __restrict__ h_in,   // [G, HID]
    float*       __restrict__ h_out)  // [G, HID]
{
    __shared__ __align__(16) float sh_h[HID];
    __shared__ float sh_u[INSZ];

    const int g   = blockIdx.y;
    const int tid = threadIdx.x;

    for (int i = tid; i < HID; i += 256)
        sh_h[i] = h_in[g * HID + i];
    if (tid < INSZ)
        sh_u[tid] = u[(g * QG - LWIN + tid + Q) & (Q - 1)];  // periodic window
    __syncthreads();

    const int warp = tid >> 5;
    const int lane = tid & 31;

    const int rpb     = (HID + gridDim.x - 1) / gridDim.x;
    const int r_begin = blockIdx.x * rpb;
    const int r_end   = min(r_begin + rpb, HID);

    for (int r = r_begin + warp; r < r_end; r += 8) {
        const float4* w4 = (const float4*)(W_hh + ((size_t)g * HID + r) * HID);
        float acc = 0.0f;
        #pragma unroll 4
        for (int j = lane; j < HID / 4; j += 32) {
            float4 wv = w4[j];
            float4 hv = *(const float4*)&sh_h[j * 4];
            acc += wv.x * hv.x + wv.y * hv.y + wv.z * hv.z + wv.w * hv.w;
        }
        const float* wi = W_in + ((size_t)g * HID + r) * INSZ;
        #pragma unroll
        for (int o = lane; o < INSZ; o += 32)
            acc += wi[o] * sh_u[o];

        #pragma unroll
        for (int off = 16; off; off >>= 1)
            acc += __shfl_xor_sync(0xffffffffu, acc, off);

        if (lane == 0)
            h_out[g * HID + r] = 0.4f * sh_h[r] + 0.6f * tanhf(acc);
    }
}

// ---------------------------------------------------------------------------
// Readout: y[g*64+o] = W_out[g,o,:] . [h ; h*h]
// grid = (QG/8, G), block = 256 (8 warps -> 8 output rows per block)
// ---------------------------------------------------------------------------
__global__ void __launch_bounds__(256) readout_kernel(
    const float* __restrict__ W_out,  // [G, QG, 2*HID]
    const float* __restrict__ h,      // [G, HID]
    float*       __restrict__ y)      // [Q]
{
    __shared__ __align__(16) float sh_h[HID];

    const int g   = blockIdx.y;
    const int tid = threadIdx.x;

    for (int i = tid; i < HID; i += 256)
        sh_h[i] = h[g * HID + i];
    __syncthreads();

    const int warp = tid >> 5;
    const int lane = tid & 31;
    const int o    = blockIdx.x * 8 + warp;   // 0..63

    const float4* w4 = (const float4*)(W_out + ((size_t)g * QG + o) * (2 * HID));
    float acc = 0.0f;
    #pragma unroll 4
    for (int j = lane; j < HID / 4; j += 32) {
        float4 wv = w4[j];
        float4 hv = *(const float4*)&sh_h[j * 4];
        acc += wv.x * hv.x + wv.y * hv.y + wv.z * hv.z + wv.w * hv.w;
    }
    #pragma unroll 4
    for (int j = lane; j < HID / 4; j += 32) {
        float4 wv = w4[HID / 4 + j];
        float4 hv = *(const float4*)&sh_h[j * 4];
        acc += wv.x * (hv.x * hv.x) + wv.y * (hv.y * hv.y)
             + wv.z * (hv.z * hv.z) + wv.w * (hv.w * hv.w);
    }

    #pragma unroll
    for (int off = 16; off; off >>= 1)
        acc += __shfl_xor_sync(0xffffffffu, acc, off);

    if (lane == 0)
        y[g * QG + o] = acc;
}

// ---------------------------------------------------------------------------
// Launch sequence: 32 warmup steps + 400 (step, readout) pairs.
// Closed-loop input u for step s>0 is the previous output row in d_out.
// All launches on the legacy default stream (graph-captured by harness).
// ---------------------------------------------------------------------------
extern "C" void kernel_launch(void* const* d_in, const int* in_sizes, int n_in,
                              void* d_out, int out_size)
{
    const float* u_hist = (const float*)d_in[0];   // [64, 512]
    const float* W_in   = (const float*)d_in[1];   // [8, 4000, 76]
    const float* W_hh   = (const float*)d_in[2];   // [8, 4000, 4000]
    const float* W_out  = (const float*)d_in[3];   // [8, 64, 8000]
    float*       out    = (float*)d_out;           // [400, 512]

    float* hbase = nullptr;
    cudaGetSymbolAddress((void**)&hbase, g_h);
    // h0 = zeros (buffer 0 only; buffer 1 is written before first read)
    cudaMemsetAsync(hbase, 0, sizeof(float) * G * HID, 0);

    const dim3 sgrid(18, G);       // 144 blocks ~ one wave on 148 SMs
    const dim3 rgrid(QG / 8, G);   // 64 blocks

    float* hb[2] = { hbase, hbase + G * HID };

    // Warmup on the last EPS history rows
    for (int t = 0; t < EPS; ++t) {
        const float* u = u_hist + (size_t)(NHIST - EPS + t) * Q;
        step_kernel<<<sgrid, 256>>>(W_in, W_hh, u, hb[t & 1], hb[(t + 1) & 1]);
    }

    // Closed-loop prediction
    for (int s = 0; s < STEPS; ++s) {
        const float* u = (s == 0) ? (u_hist + (size_t)(NHIST - 1) * Q)
                                  : (out + (size_t)(s - 1) * Q);
        step_kernel<<<sgrid, 256>>>(W_in, W_hh, u, hb[s & 1], hb[(s + 1) & 1]);
        readout_kernel<<<rgrid, 256>>>(W_out, hb[(s + 1) & 1], out + (size_t)s * Q);
    }
}

// round 2
// speedup vs baseline: 2.4304x; 2.4304x over previous
#include <cuda_runtime.h>
#include <math.h>

// Problem constants (fixed by setup_inputs)
#define G     8
#define HID   4000
#define Q     512
#define QG    64      // Q / G
#define LWIN  6       // L
#define INSZ  76      // QG + 2*L
#define STEPS 400
#define EPS   32
#define NHIST 64      // u_hist rows

#define CHUNKS 125          // blocks per group for step kernel
#define RPB    32           // rows per block (CHUNKS * RPB == HID)

// Double-buffered hidden state (scratch)
__device__ float g_h[2][G * HID];

// ---------------------------------------------------------------------------
// One ESN step: h_out = 0.4*h_in + 0.6*tanh(W_in@ug + W_hh@h_in)
// grid = (CHUNKS, G), block = 256. 8 warps * 4 rows = 32 rows per block.
// Each warp processes 2 rows at once (dual accumulators -> 2x load streams,
// shared h value reused for both rows).
// ---------------------------------------------------------------------------
__global__ void __launch_bounds__(256) step_kernel(
    const float* __restrict__ W_in,   // [G, HID, INSZ]
    const float* __restrict__ W_hh,   // [G, HID, HID]
    const float* __restrict__ u,      // [Q] (current input vector)
    const float* __restrict__ h_in,   // [G, HID]
    float*       __restrict__ h_out)  // [G, HID]
{
    __shared__ __align__(16) float sh_h[HID];
    __shared__ float sh_u[INSZ];

    const int g   = blockIdx.y;
    const int tid = threadIdx.x;

    for (int i = tid; i < HID; i += 256)
        sh_h[i] = h_in[g * HID + i];
    if (tid < INSZ)
        sh_u[tid] = u[(g * QG - LWIN + tid + Q) & (Q - 1)];  // periodic window
    __syncthreads();

    const int warp = tid >> 5;
    const int lane = tid & 31;
    const int rbase = blockIdx.x * RPB + warp * 4;   // this warp owns 4 rows

    const float4* sh4 = (const float4*)sh_h;

    #pragma unroll
    for (int p = 0; p < 2; ++p) {
        const int r = rbase + 2 * p;
        const float4* wa = (const float4*)(W_hh + ((size_t)g * HID + r) * HID);
        const float4* wb = wa + HID / 4;

        float acc0 = 0.0f, acc1 = 0.0f;
        #pragma unroll 4
        for (int j = lane; j < HID / 4; j += 32) {
            float4 hv = sh4[j];
            float4 av = wa[j];
            float4 bv = wb[j];
            acc0 += av.x * hv.x + av.y * hv.y + av.z * hv.z + av.w * hv.w;
            acc1 += bv.x * hv.x + bv.y * hv.y + bv.z * hv.z + bv.w * hv.w;
        }

        const float* wi = W_in + ((size_t)g * HID + r) * INSZ;
        #pragma unroll
        for (int o = lane; o < INSZ; o += 32) {
            acc0 += wi[o] * sh_u[o];
            acc1 += wi[INSZ + o] * sh_u[o];
        }

        #pragma unroll
        for (int off = 16; off; off >>= 1) {
            acc0 += __shfl_xor_sync(0xffffffffu, acc0, off);
            acc1 += __shfl_xor_sync(0xffffffffu, acc1, off);
        }

        if (lane == 0) {
            h_out[g * HID + r]     = 0.4f * sh_h[r]     + 0.6f * tanhf(acc0);
            h_out[g * HID + r + 1] = 0.4f * sh_h[r + 1] + 0.6f * tanhf(acc1);
        }
    }
}

// ---------------------------------------------------------------------------
// Readout: y[g*64+o] = W_out[g,o,:] . [h ; h*h]
// grid = (QG, G) = 512 blocks, block = 256. One block per output element,
// block-wide reduction.
// ---------------------------------------------------------------------------
__global__ void __launch_bounds__(256) readout_kernel(
    const float* __restrict__ W_out,  // [G, QG, 2*HID]
    const float* __restrict__ h,      // [G, HID]
    float*       __restrict__ y)      // [Q]
{
    __shared__ __align__(16) float sh_h[HID];
    __shared__ float sh_red[8];

    const int g   = blockIdx.y;
    const int o   = blockIdx.x;
    const int tid = threadIdx.x;

    for (int i = tid; i < HID; i += 256)
        sh_h[i] = h[g * HID + i];
    __syncthreads();

    const float4* sh4 = (const float4*)sh_h;
    const float4* w4  = (const float4*)(W_out + ((size_t)g * QG + o) * (2 * HID));

    float acc = 0.0f;
    #pragma unroll 2
    for (int j = tid; j < HID / 4; j += 256) {
        float4 wv = w4[j];
        float4 hv = sh4[j];
        acc += wv.x * hv.x + wv.y * hv.y + wv.z * hv.z + wv.w * hv.w;
    }
    #pragma unroll 2
    for (int j = tid; j < HID / 4; j += 256) {
        float4 wv = w4[HID / 4 + j];
        float4 hv = sh4[j];
        acc += wv.x * (hv.x * hv.x) + wv.y * (hv.y * hv.y)
             + wv.z * (hv.z * hv.z) + wv.w * (hv.w * hv.w);
    }

    const int warp = tid >> 5;
    const int lane = tid & 31;
    #pragma unroll
    for (int off = 16; off; off >>= 1)
        acc += __shfl_xor_sync(0xffffffffu, acc, off);
    if (lane == 0) sh_red[warp] = acc;
    __syncthreads();
    if (warp == 0) {
        float v = (lane < 8) ? sh_red[lane] : 0.0f;
        #pragma unroll
        for (int off = 4; off; off >>= 1)
            v += __shfl_xor_sync(0xffffffffu, v, off);
        if (lane == 0) y[g * QG + o] = v;
    }
}

// ---------------------------------------------------------------------------
// Launch sequence: 32 warmup steps + 400 (step, readout) pairs.
// ---------------------------------------------------------------------------
extern "C" void kernel_launch(void* const* d_in, const int* in_sizes, int n_in,
                              void* d_out, int out_size)
{
    const float* u_hist = (const float*)d_in[0];   // [64, 512]
    const float* W_in   = (const float*)d_in[1];   // [8, 4000, 76]
    const float* W_hh   = (const float*)d_in[2];   // [8, 4000, 4000]
    const float* W_out  = (const float*)d_in[3];   // [8, 64, 8000]
    float*       out    = (float*)d_out;           // [400, 512]

    float* hbase = nullptr;
    cudaGetSymbolAddress((void**)&hbase, g_h);
    cudaMemsetAsync(hbase, 0, sizeof(float) * G * HID, 0);

    const dim3 sgrid(CHUNKS, G);   // 1000 blocks
    const dim3 rgrid(QG, G);       // 512 blocks

    float* hb[2] = { hbase, hbase + G * HID };

    for (int t = 0; t < EPS; ++t) {
        const float* u = u_hist + (size_t)(NHIST - EPS + t) * Q;
        step_kernel<<<sgrid, 256>>>(W_in, W_hh, u, hb[t & 1], hb[(t + 1) & 1]);
    }

    for (int s = 0; s < STEPS; ++s) {
        const float* u = (s == 0) ? (u_hist + (size_t)(NHIST - 1) * Q)
                                  : (out + (size_t)(s - 1) * Q);
        step_kernel<<<sgrid, 256>>>(W_in, W_hh, u, hb[s & 1], hb[(s + 1) & 1]);
        readout_kernel<<<rgrid, 256>>>(W_out, hb[(s + 1) & 1], out + (size_t)s * Q);
    }
}

// round 4
// speedup vs baseline: 4.6300x; 1.9051x over previous
#include <cuda_runtime.h>
#include <math.h>
#include <stdint.h>

// Problem constants (fixed by setup_inputs)
#define G     8
#define HID   4000
#define Q     512
#define QG    64      // Q / G
#define LWIN  6       // L
#define INSZ  76      // QG + 2*L
#define STEPS 400
#define EPS   32
#define NHIST 64      // u_hist rows

#define NROWS (G * HID)          // 32000 weight rows
#define NI4   (HID / 8)          // 500 int4 (8 shorts) per row

// Scratch: double-buffered hidden state, quantized W_hh, per-row dequant scale
__device__ float g_h[2][G * HID];
__device__ short g_Wq[(size_t)G * HID * HID];   // 256 MB int16 weights
__device__ float g_ds[NROWS];                   // dequant scale per row

// ---------------------------------------------------------------------------
// Quantize W_hh rows to int16 with per-row absmax scaling.
// grid = NROWS/8 blocks, block = 256 (8 warps, one row per warp).
// ---------------------------------------------------------------------------
__global__ void __launch_bounds__(256) quant_kernel(const float* __restrict__ W_hh)
{
    const int warp = threadIdx.x >> 5;
    const int lane = threadIdx.x & 31;
    const int row  = blockIdx.x * 8 + warp;

    const float4* w4 = (const float4*)(W_hh + (size_t)row * HID);

    // pass 1: row absmax
    float m = 0.0f;
    for (int j = lane; j < HID / 4; j += 32) {
        float4 v = w4[j];
        m = fmaxf(m, fmaxf(fmaxf(fabsf(v.x), fabsf(v.y)),
                           fmaxf(fabsf(v.z), fabsf(v.w))));
    }
    #pragma unroll
    for (int off = 16; off; off >>= 1)
        m = fmaxf(m, __shfl_xor_sync(0xffffffffu, m, off));

    const float qs = (m > 0.0f) ? (32767.0f / m) : 0.0f;
    if (lane == 0)
        g_ds[row] = (m > 0.0f) ? (m / 32767.0f) : 0.0f;

    // pass 2: quantize + pack 4 shorts per uint2
    uint2* dst = (uint2*)(g_Wq + (size_t)row * HID);
    for (int j = lane; j < HID / 4; j += 32) {
        float4 v = w4[j];
        int s0 = __float2int_rn(fminf(fmaxf(v.x * qs, -32767.0f), 32767.0f));
        int s1 = __float2int_rn(fminf(fmaxf(v.y * qs, -32767.0f), 32767.0f));
        int s2 = __float2int_rn(fminf(fmaxf(v.z * qs, -32767.0f), 32767.0f));
        int s3 = __float2int_rn(fminf(fmaxf(v.w * qs, -32767.0f), 32767.0f));
        uint2 p;
        p.x = (s0 & 0xffff) | (s1 << 16);
        p.y = (s2 & 0xffff) | (s3 << 16);
        dst[j] = p;
    }
}

// 8 int16 weights (one int4) against 8 h values (two float4)
__device__ __forceinline__ void dotq(int4 w, float4 ha, float4 hb, float& acc)
{
    acc += (float)((short)w.x) * ha.x + (float)(w.x >> 16) * ha.y;
    acc += (float)((short)w.y) * ha.z + (float)(w.y >> 16) * ha.w;
    acc += (float)((short)w.z) * hb.x + (float)(w.z >> 16) * hb.y;
    acc += (float)((short)w.w) * hb.z + (float)(w.w >> 16) * hb.w;
}

// ---------------------------------------------------------------------------
// One ESN step with int16 W_hh:
//   h_out = 0.4*h_in + 0.6*tanh(ds*(Wq@h_in) + W_in@ug)
// grid = (125, G), block = 256. 8 warps * 4 rows = 32 rows/block.
// Each warp streams 4 rows simultaneously (4 independent LDG.128 streams).
// ---------------------------------------------------------------------------
__global__ void __launch_bounds__(256, 5) step_kernel(
    const float* __restrict__ W_in,   // [G, HID, INSZ]
    const float* __restrict__ u,      // [Q]
    const float* __restrict__ h_in,   // [G, HID]
    float*       __restrict__ h_out)  // [G, HID]
{
    __shared__ __align__(16) float sh_h[HID];
    __shared__ float sh_u[INSZ];

    const int g   = blockIdx.y;
    const int tid = threadIdx.x;

    for (int i = tid; i < HID; i += 256)
        sh_h[i] = h_in[g * HID + i];
    if (tid < INSZ)
        sh_u[tid] = u[(g * QG - LWIN + tid + Q) & (Q - 1)];  // periodic window
    __syncthreads();

    const int warp = tid >> 5;
    const int lane = tid & 31;
    const int r0   = blockIdx.x * 32 + warp * 4;   // this warp owns rows r0..r0+3
    const int grow = g * HID + r0;

    const int4* w0 = (const int4*)(g_Wq + (size_t)grow * HID);
    const int4* w1 = (const int4*)(g_Wq + (size_t)(grow + 1) * HID);
    const int4* w2 = (const int4*)(g_Wq + (size_t)(grow + 2) * HID);
    const int4* w3 = (const int4*)(g_Wq + (size_t)(grow + 3) * HID);
    const float4* sh4 = (const float4*)sh_h;

    float acc0 = 0.0f, acc1 = 0.0f, acc2 = 0.0f, acc3 = 0.0f;

    for (int j = lane; j < NI4; j += 32) {
        int4 a = w0[j];
        int4 b = w1[j];
        int4 c = w2[j];
        int4 d = w3[j];
        float4 ha = sh4[2 * j];
        float4 hb = sh4[2 * j + 1];
        dotq(a, ha, hb, acc0);
        dotq(b, ha, hb, acc1);
        dotq(c, ha, hb, acc2);
        dotq(d, ha, hb, acc3);
    }

    // dequant scale, then add fp32 W_in contribution
    acc0 *= g_ds[grow];
    acc1 *= g_ds[grow + 1];
    acc2 *= g_ds[grow + 2];
    acc3 *= g_ds[grow + 3];

    const float* wi = W_in + (size_t)grow * INSZ;
    #pragma unroll
    for (int o = lane; o < INSZ; o += 32) {
        float uo = sh_u[o];
        acc0 += wi[o] * uo;
        acc1 += wi[INSZ + o] * uo;
        acc2 += wi[2 * INSZ + o] * uo;
        acc3 += wi[3 * INSZ + o] * uo;
    }

    #pragma unroll
    for (int off = 16; off; off >>= 1) {
        acc0 += __shfl_xor_sync(0xffffffffu, acc0, off);
        acc1 += __shfl_xor_sync(0xffffffffu, acc1, off);
        acc2 += __shfl_xor_sync(0xffffffffu, acc2, off);
        acc3 += __shfl_xor_sync(0xffffffffu, acc3, off);
    }

    if (lane < 4) {
        float a = (lane == 0) ? acc0 : (lane == 1) ? acc1 : (lane == 2) ? acc2 : acc3;
        int   r = r0 + lane;
        h_out[g * HID + r] = 0.4f * sh_h[r] + 0.6f * tanhf(a);
    }
}

// ---------------------------------------------------------------------------
// Readout: y[g*64+o] = W_out[g,o,:] . [h ; h*h]   (fp32, tiny)
// grid = (QG, G), block = 256. One block per output element.
// ---------------------------------------------------------------------------
__global__ void __launch_bounds__(256) readout_kernel(
    const float* __restrict__ W_out,  // [G, QG, 2*HID]
    const float* __restrict__ h,      // [G, HID]
    float*       __restrict__ y)      // [Q]
{
    __shared__ __align__(16) float sh_h[HID];
    __shared__ float sh_red[8];

    const int g   = blockIdx.y;
    const int o   = blockIdx.x;
    const int tid = threadIdx.x;

    for (int i = tid; i < HID; i += 256)
        sh_h[i] = h[g * HID + i];
    __syncthreads();

    const float4* sh4 = (const float4*)sh_h;
    const float4* w4  = (const float4*)(W_out + ((size_t)g * QG + o) * (2 * HID));

    float acc = 0.0f;
    #pragma unroll 2
    for (int j = tid; j < HID / 4; j += 256) {
        float4 wv = w4[j];
        float4 hv = sh4[j];
        acc += wv.x * hv.x + wv.y * hv.y + wv.z * hv.z + wv.w * hv.w;
    }
    #pragma unroll 2
    for (int j = tid; j < HID / 4; j += 256) {
        float4 wv = w4[HID / 4 + j];
        float4 hv = sh4[j];
        acc += wv.x * (hv.x * hv.x) + wv.y * (hv.y * hv.y)
             + wv.z * (hv.z * hv.z) + wv.w * (hv.w * hv.w);
    }

    const int warp = tid >> 5;
    const int lane = tid & 31;
    #pragma unroll
    for (int off = 16; off; off >>= 1)
        acc += __shfl_xor_sync(0xffffffffu, acc, off);
    if (lane == 0) sh_red[warp] = acc;
    __syncthreads();
    if (warp == 0) {
        float v = (lane < 8) ? sh_red[lane] : 0.0f;
        #pragma unroll
        for (int off = 4; off; off >>= 1)
            v += __shfl_xor_sync(0xffffffffu, v, off);
        if (lane == 0) y[g * QG + o] = v;
    }
}

// ---------------------------------------------------------------------------
// Launch sequence: quantize, 32 warmup steps, 400 (step, readout) pairs.
// ---------------------------------------------------------------------------
extern "C" void kernel_launch(void* const* d_in, const int* in_sizes, int n_in,
                              void* d_out, int out_size)
{
    const float* u_hist = (const float*)d_in[0];   // [64, 512]
    const float* W_in   = (const float*)d_in[1];   // [8, 4000, 76]
    const float* W_hh   = (const float*)d_in[2];   // [8, 4000, 4000]
    const float* W_out  = (const float*)d_in[3];   // [8, 64, 8000]
    float*       out    = (float*)d_out;           // [400, 512]

    float* hbase = nullptr;
    cudaGetSymbolAddress((void**)&hbase, g_h);
    cudaMemsetAsync(hbase, 0, sizeof(float) * G * HID, 0);

    quant_kernel<<<NROWS / 8, 256>>>(W_hh);

    const dim3 sgrid(125, G);      // 1000 blocks
    const dim3 rgrid(QG, G);       // 512 blocks

    float* hb[2] = { hbase, hbase + G * HID };

    for (int t = 0; t < EPS; ++t) {
        const float* u = u_hist + (size_t)(NHIST - EPS + t) * Q;
        step_kernel<<<sgrid, 256>>>(W_in, u, hb[t & 1], hb[(t + 1) & 1]);
    }

    for (int s = 0; s < STEPS; ++s) {
        const float* u = (s == 0) ? (u_hist + (size_t)(NHIST - 1) * Q)
                                  : (out + (size_t)(s - 1) * Q);
        step_kernel<<<sgrid, 256>>>(W_in, u, hb[s & 1], hb[(s + 1) & 1]);
        readout_kernel<<<rgrid, 256>>>(W_out, hb[(s + 1) & 1], out + (size_t)s * Q);
    }
}